// round 15
// baseline (speedup 1.0000x reference)
#include <cuda_runtime.h>
#include <cuda_bf16.h>
#include <cuda_fp16.h>
#include <math.h>
#include <stdint.h>

#define B_    2
#define S_    2048
#define E_    2048
#define H_    16
#define HKV_  4
#define D_    128
#define QKV_  3072
#define T_    (B_*S_)      // 4096
#define HROT  64           // ROT_DIM/2

// ---------------- scratch ----------------------------------------------------
__device__ __half g_qkvh[T_*QKV_];            // after GEMM1 (fp16)
__device__ __half g_xh[T_*E_];                // x as fp16
__device__ __half g_w1h[QKV_*E_];             // W_in^T fp16
__device__ __half g_w2h[E_*E_];               // W_out^T fp16
__device__ __half g_ch[T_*E_];                // ctx fp16
__device__ __half g_qh[T_*H_*D_];             // q fp16 (scaled, roped)
__device__ __half g_kh[T_*HKV_*D_];           // k fp16 (roped)
__device__ __half g_vh[T_*HKV_*D_];           // v fp16
__device__ float g_cos [S_*HROT];
__device__ float g_sin [S_*HROT];

// ---------------- helpers ---------------------------------------------------
__device__ __forceinline__ uint32_t su32(const void* p) {
    return (uint32_t)__cvta_generic_to_shared(p);
}
__device__ __forceinline__ void cp16(uint32_t dst, const void* src) {
    asm volatile("cp.async.cg.shared.global [%0], [%1], 16;\n"
                 :: "r"(dst), "l"(__cvta_generic_to_global(src)) : "memory");
}
__device__ __forceinline__ void mma16816h(float* c, const uint32_t* a, const uint32_t* b) {
    asm volatile(
        "mma.sync.aligned.m16n8k16.row.col.f32.f16.f16.f32 "
        "{%0,%1,%2,%3}, {%4,%5,%6,%7}, {%8,%9}, {%0,%1,%2,%3};"
        : "+f"(c[0]), "+f"(c[1]), "+f"(c[2]), "+f"(c[3])
        : "r"(a[0]), "r"(a[1]), "r"(a[2]), "r"(a[3]), "r"(b[0]), "r"(b[1]));
}
__device__ __forceinline__ void ldmx4(uint32_t* r, uint32_t addr) {
    asm volatile("ldmatrix.sync.aligned.m8n8.x4.shared.b16 {%0,%1,%2,%3}, [%4];"
                 : "=r"(r[0]), "=r"(r[1]), "=r"(r[2]), "=r"(r[3]) : "r"(addr));
}
__device__ __forceinline__ void ldmx4t(uint32_t* r, uint32_t addr) {
    asm volatile("ldmatrix.sync.aligned.m8n8.x4.trans.shared.b16 {%0,%1,%2,%3}, [%4];"
                 : "=r"(r[0]), "=r"(r[1]), "=r"(r[2]), "=r"(r[3]) : "r"(addr));
}
__device__ __forceinline__ uint32_t pack_f16(float a, float b) {
    __half2 v = __floats2half2_rn(a, b);
    return *(uint32_t*)&v;
}

// ---------------- rotary tables (double exp for inv_freq, float trig) --------
__global__ void rope_table_kernel() {
    int idx = blockIdx.x * blockDim.x + threadIdx.x;
    if (idx >= S_*HROT) return;
    int i = idx % HROT;
    int s = idx / HROT;
    const double L = 9.210340371976184; // ln(10000)
    double inv_d = exp(-(double)i / 64.0 * L);
    float  inv_f = (float)inv_d;
    float  ang_f = __fmul_rn((float)s, inv_f); // float32 angle like numpy
    g_cos[idx] = cosf(ang_f);
    g_sin[idx] = sinf(ang_f);
}

// ---------------- x -> fp16 --------------------------------------------------
__global__ void split_x_kernel(const float* __restrict__ x) {
    int idx = blockIdx.x * blockDim.x + threadIdx.x;
    if (idx >= T_*E_) return;
    g_xh[idx] = __float2half(x[idx]);
}

// ---------------- transpose weights -> fp16: W[R][C] -> Wt[C][R] -------------
__global__ void transpose_h_kernel(const float* __restrict__ W,
                                   __half* __restrict__ Th, int R, int C) {
    __shared__ float tile[32][33];
    int c0 = blockIdx.x * 32, r0 = blockIdx.y * 32;
    for (int j = threadIdx.y; j < 32; j += 8)
        tile[j][threadIdx.x] = W[(size_t)(r0 + j) * C + c0 + threadIdx.x];
    __syncthreads();
    for (int j = threadIdx.y; j < 32; j += 8)
        Th[(size_t)(c0 + j) * R + r0 + threadIdx.x] = __float2half(tile[threadIdx.x][j]);
}

// ---------------- fp16 GEMM: 128x128 tile, 2 CTAs/SM, 3-stage ring ----------
// (at the legacy-HMMA instruction-rate ceiling — frozen)
// Ch != nullptr -> write fp16 to Ch; else write fp32 to C.
#define G3STR 144
#define G3A (128*G3STR)        // 18432
#define G3STAGE (2*G3A)        // 36864
#define GEMMH_SMEM (3*G3STAGE) // 110592

__global__ __launch_bounds__(256, 2) void gemm_fp16(
    const __half* __restrict__ A, const __half* __restrict__ Bm,
    const float* __restrict__ bias, float* __restrict__ C,
    __half* __restrict__ Ch, int N)
{
    extern __shared__ char sm8[];
    int tid = threadIdx.x, lane = tid & 31, wid = tid >> 5;
    int g = lane >> 2, tg = lane & 3;
    int wm = wid & 1, wn = wid >> 1;          // 2m x 4n
    int m0 = blockIdx.y * 128, n0 = blockIdx.x * 128;
    uint32_t smb = su32(sm8);

    float acc[4][4][4];
    #pragma unroll
    for (int mi = 0; mi < 4; mi++)
        #pragma unroll
        for (int nj = 0; nj < 4; nj++)
            #pragma unroll
            for (int q = 0; q < 4; q++) acc[mi][nj][q] = 0.f;

    auto issue = [&](int chunk, int s) {
        uint32_t bb = smb + s * G3STAGE;
        int k0 = chunk * 64;
        #pragma unroll
        for (int j = 0; j < 8; j++) {
            int idx = tid + j * 256;
            if (idx < 1024) {
                int r = idx >> 3, c = idx & 7;
                cp16(bb + r * G3STR + c * 16,
                     A + (size_t)(m0 + r) * 2048 + k0 + c * 8);
            } else {
                int o = idx - 1024;
                int r = o >> 3, c = o & 7;
                cp16(bb + G3A + r * G3STR + c * 16,
                     Bm + (size_t)(n0 + r) * 2048 + k0 + c * 8);
            }
        }
        asm volatile("cp.async.commit_group;\n" ::: "memory");
    };

    uint32_t a_base = (uint32_t)(wm * 64 + (lane & 15)) * G3STR + (lane >> 4) * 16;
    uint32_t b_base = (uint32_t)(wn * 32 + (lane & 7) + ((lane >> 4) * 8)) * G3STR
                    + ((lane >> 3) & 1) * 16;

    issue(0, 0);
    issue(1, 1);
    for (int i = 0; i < 32; i++) {
        if (i < 30) {
            asm volatile("cp.async.wait_group 1;\n" ::: "memory");
        } else {
            asm volatile("cp.async.wait_group 0;\n" ::: "memory");
        }
        __syncthreads();
        if (i < 30) issue(i + 2, (i + 2) % 3);

        uint32_t uA = smb + (i % 3) * G3STAGE;
        uint32_t uB = uA + G3A;

        #pragma unroll
        for (int ks = 0; ks < 4; ks++) {
            int kb = ks * 32;   // bytes
            uint32_t af[4][4], bf[4][2];
            #pragma unroll
            for (int mi = 0; mi < 4; mi++)
                ldmx4(af[mi], uA + a_base + mi * 16 * G3STR + kb);
            #pragma unroll
            for (int njp = 0; njp < 2; njp++)
                ldmx4(&bf[njp*2][0], uB + b_base + njp * 16 * G3STR + kb);
            #pragma unroll
            for (int mi = 0; mi < 4; mi++)
                #pragma unroll
                for (int nj = 0; nj < 4; nj++)
                    mma16816h(acc[mi][nj], af[mi], bf[nj]);
        }
    }

    #pragma unroll
    for (int mi = 0; mi < 4; mi++)
        #pragma unroll
        for (int nj = 0; nj < 4; nj++) {
            int row = m0 + wm * 64 + mi * 16 + g;
            int col = n0 + wn * 32 + nj * 8 + tg * 2;
            float b0v = bias[col], b1v = bias[col + 1];
            float o00 = acc[mi][nj][0] + b0v, o01 = acc[mi][nj][1] + b1v;
            float o10 = acc[mi][nj][2] + b0v, o11 = acc[mi][nj][3] + b1v;
            if (Ch) {
                *(uint32_t*)(Ch + (size_t)row * N + col)       = pack_f16(o00, o01);
                *(uint32_t*)(Ch + (size_t)(row + 8) * N + col) = pack_f16(o10, o11);
            } else {
                float2 v0 = { o00, o01 };
                float2 v1 = { o10, o11 };
                *(float2*)(C + (size_t)row * N + col) = v0;
                *(float2*)(C + (size_t)(row + 8) * N + col) = v1;
            }
        }
}

// ---------------- tiled conv + rope -> fp16 q/k/v (fp16 qkv input) ----------
__global__ __launch_bounds__(256) void conv_rope_tiled(
    const float* __restrict__ conv_w, const float* __restrict__ conv_b)
{
    __shared__ float tile[35*128];
    __shared__ float cw[128*4];
    __shared__ float cb[128];

    int tid = threadIdx.x;
    int t0  = blockIdx.x * 32;
    int hb  = blockIdx.y;            // 0..23
    int c0  = hb * 128;
    int b   = t0 / S_;
    int s0  = t0 % S_;
    const float scale = 0.08838834764831845f; // 1/sqrt(128)

    for (int i = tid; i < 512; i += 256) cw[i] = conv_w[c0*4 + i];
    if (tid < 128) cb[tid] = conv_b[c0 + tid];

    for (int i = tid; i < 35*128; i += 256) {
        int r = i >> 7, c = i & 127;
        int s = s0 + r - 3;
        tile[i] = (s >= 0)
            ? __half2float(g_qkvh[(size_t)(b*S_ + s)*QKV_ + c0 + c]) : 0.f;
    }
    __syncthreads();

    if (hb < 20) {
        #pragma unroll
        for (int p = tid; p < 32*64; p += 256) {
            int sl = p >> 6, i = p & 63;
            int s = s0 + sl;
            float a1 = cb[i], a2 = cb[i + 64];
            #pragma unroll
            for (int k = 0; k < 4; k++) {
                a1 = fmaf(tile[(sl + k)*128 + i],      cw[i*4 + k],        a1);
                a2 = fmaf(tile[(sl + k)*128 + i + 64], cw[(i + 64)*4 + k], a2);
            }
            float cs = g_cos[s*HROT + i], sn = g_sin[s*HROT + i];
            float r1 = a1*cs - a2*sn;
            float r2 = a2*cs + a1*sn;
            if (hb < 16) {
                r1 *= scale; r2 *= scale;
                size_t o = (size_t)(b*S_ + s)*2048 + hb*128 + i;
                g_qh[o]    = __float2half(r1);
                g_qh[o+64] = __float2half(r2);
            } else {
                size_t o = (size_t)(b*S_ + s)*512 + (hb - 16)*128 + i;
                g_kh[o]    = __float2half(r1);
                g_kh[o+64] = __float2half(r2);
            }
        }
    } else {
        #pragma unroll
        for (int p = tid; p < 32*128; p += 256) {
            int sl = p >> 7, c = p & 127;
            int s = s0 + sl;
            float a1 = cb[c];
            #pragma unroll
            for (int k = 0; k < 4; k++)
                a1 = fmaf(tile[(sl + k)*128 + c], cw[c*4 + k], a1);
            g_vh[(size_t)(b*S_ + s)*512 + (hb - 20)*128 + c] = __float2half(a1);
        }
    }
}

// ---------------- HMMA flash attention (causal, GQA), all fp16 --------------
// 2-stage KV ring, 1 sync/kb, 2 CTAs/SM (round-11 design, clean-env retest).
#define ASTR 136                       // halves per smem row
#define ASTRB 272                      // bytes per smem row
#define AQ_ELEMS (128*ASTR)            // 17408 halves
#define AKV_ELEMS (2*64*ASTR)          // 17408 halves (K + V)
#define ATTN_SMEM ((AQ_ELEMS + 2*AKV_ELEMS) * 2)   // 104448 bytes

__global__ __launch_bounds__(256, 2) void attn_mma() {
    extern __shared__ __half smH[];
    __half* sQ = smH;

    int tid = threadIdx.x, lane = tid & 31, w = tid >> 5;
    int g = lane >> 2, tg = lane & 3;
    int qblk = 15 - (int)blockIdx.x;
    int h = blockIdx.y, b = blockIdx.z;
    int hkv = h >> 2;
    int q0 = qblk * 128;
    size_t bS = (size_t)b * S_;

    // ---- issue Q ----
    {
        #pragma unroll
        for (int j = 0; j < 8; j++) {
            int i = tid + j * 256;
            int r = i >> 4, c = i & 15;
            cp16(su32(sQ + r * ASTR + c * 8),
                 g_qh + (bS + q0 + r) * 2048 + h * 128 + c * 8);
        }
        asm volatile("cp.async.commit_group;\n" ::: "memory");
    }

    auto issueKV = [&](int kb, int buf) {
        __half* kv = smH + AQ_ELEMS + buf * AKV_ELEMS;
        int k0 = kb * 64;
        #pragma unroll
        for (int j = 0; j < 8; j++) {
            int i = tid + j * 256;
            int arr = i >> 10, o = i & 1023;
            int r = o >> 4, c = o & 15;
            size_t off = (bS + k0 + r) * 512 + hkv * 128 + c * 8;
            const __half* src = (arr == 0) ? (g_kh + off) : (g_vh + off);
            cp16(su32(kv + arr * (64*ASTR) + r * ASTR + c * 8), src);
        }
        asm volatile("cp.async.commit_group;\n" ::: "memory");
    };

    float oc[16][4];
    #pragma unroll
    for (int n = 0; n < 16; n++)
        #pragma unroll
        for (int q = 0; q < 4; q++) oc[n][q] = 0.f;
    float m0 = -1e30f, m1 = -1e30f, l0 = 0.f, l1 = 0.f;

    int nkb = 2 * qblk + 2;
    issueKV(0, 0);

    int row0 = q0 + w * 16;

    // ldmatrix lane addressing (bytes)
    uint32_t q_lm = (uint32_t)(w * 16 + (lane & 15)) * ASTRB + (lane >> 4) * 16;
    uint32_t k_lm = (uint32_t)((lane & 7) + ((lane >> 4) * 8)) * ASTRB
                  + ((lane >> 3) & 1) * 16;

    // V ldmatrix.trans lane components (half units)
    int v_t  = lane >> 3;
    int v_kr = ((v_t & 1) << 3) + (lane & 7);
    int v_dc = (v_t >> 1) << 3;

    uint32_t uQ = su32(smH);

    for (int kb = 0; kb < nkb; kb++) {
        asm volatile("cp.async.wait_group 0;\n" ::: "memory");
        __syncthreads();
        if (kb + 1 < nkb) issueKV(kb + 1, (kb + 1) & 1);

        int k0 = kb * 64;
        bool active = (k0 <= row0 + 15);
        if (active) {
            __half* sV = smH + AQ_ELEMS + (kb & 1) * AKV_ELEMS + 64*ASTR;
            uint32_t uK = uQ + (AQ_ELEMS + (kb & 1) * AKV_ELEMS) * 2;

            float sc[8][4];
            #pragma unroll
            for (int j = 0; j < 8; j++)
                #pragma unroll
                for (int q = 0; q < 4; q++) sc[j][q] = 0.f;

            // ---- S = Q K^T (fp16, ldmatrix frags) ----
            #pragma unroll
            for (int ks = 0; ks < 8; ks++) {
                int kbyte = ks * 32;
                uint32_t qf[4], kf[8][2];
                ldmx4(qf, uQ + q_lm + kbyte);
                #pragma unroll
                for (int npk = 0; npk < 4; npk++)
                    ldmx4(&kf[npk*2][0], uK + k_lm + npk * 16 * ASTRB + kbyte);
                #pragma unroll
                for (int j = 0; j < 8; j++)
                    mma16816h(sc[j], qf, kf[j]);
            }

            // ---- causal mask (boundary tiles only) ----
            if (k0 + 63 > row0) {
                #pragma unroll
                for (int j = 0; j < 8; j++) {
                    int col = k0 + j*8 + tg*2;
                    int r0r = row0 + g, r1r = row0 + g + 8;
                    if (col     > r0r) sc[j][0] = -1e30f;
                    if (col + 1 > r0r) sc[j][1] = -1e30f;
                    if (col     > r1r) sc[j][2] = -1e30f;
                    if (col + 1 > r1r) sc[j][3] = -1e30f;
                }
            }

            // ---- online softmax (rows g, g+8; reduce over tg quad) ----
            float nm0 = -1e30f, nm1 = -1e30f;
            #pragma unroll
            for (int j = 0; j < 8; j++) {
                nm0 = fmaxf(nm0, fmaxf(sc[j][0], sc[j][1]));
                nm1 = fmaxf(nm1, fmaxf(sc[j][2], sc[j][3]));
            }
            nm0 = fmaxf(nm0, __shfl_xor_sync(0xffffffff, nm0, 1));
            nm0 = fmaxf(nm0, __shfl_xor_sync(0xffffffff, nm0, 2));
            nm1 = fmaxf(nm1, __shfl_xor_sync(0xffffffff, nm1, 1));
            nm1 = fmaxf(nm1, __shfl_xor_sync(0xffffffff, nm1, 2));
            float mn0 = fmaxf(m0, nm0), mn1 = fmaxf(m1, nm1);
            float fac0 = __expf(m0 - mn0), fac1 = __expf(m1 - mn1);
            m0 = mn0; m1 = mn1;

            float sum0 = 0.f, sum1 = 0.f;
            uint32_t ph[8][2];
            #pragma unroll
            for (int j = 0; j < 8; j++) {
                float p0 = __expf(sc[j][0] - mn0);
                float p1 = __expf(sc[j][1] - mn0);
                float p2 = __expf(sc[j][2] - mn1);
                float p3 = __expf(sc[j][3] - mn1);
                sum0 += p0 + p1; sum1 += p2 + p3;
                ph[j][0] = pack_f16(p0, p1);
                ph[j][1] = pack_f16(p2, p3);
            }
            sum0 += __shfl_xor_sync(0xffffffff, sum0, 1);
            sum0 += __shfl_xor_sync(0xffffffff, sum0, 2);
            sum1 += __shfl_xor_sync(0xffffffff, sum1, 1);
            sum1 += __shfl_xor_sync(0xffffffff, sum1, 2);
            l0 = l0 * fac0 + sum0;
            l1 = l1 * fac1 + sum1;

            #pragma unroll
            for (int n = 0; n < 16; n++) {
                oc[n][0] *= fac0; oc[n][1] *= fac0;
                oc[n][2] *= fac1; oc[n][3] *= fac1;
            }

            // ---- O += P V (fp16), V via ldmatrix.trans ----
            #pragma unroll
            for (int kc = 0; kc < 4; kc++) {
                uint32_t ah[4] = { ph[2*kc][0], ph[2*kc][1], ph[2*kc+1][0], ph[2*kc+1][1] };
                #pragma unroll
                for (int np = 0; np < 8; np++) {
                    int vo = (kc*16 + v_kr) * ASTR + np*16 + v_dc;
                    uint32_t vh[4];
                    ldmx4t(vh, su32(sV + vo));
                    mma16816h(oc[2*np],     ah, vh);
                    mma16816h(oc[2*np + 1], ah, vh + 2);
                }
            }
        }
    }

    // ---- epilogue: normalize + fp16 ctx write ----
    float il0 = 1.0f / l0, il1 = 1.0f / l1;
    size_t ro0 = (bS + row0 + g) * 2048 + h * 128 + tg * 2;
    size_t ro1 = (bS + row0 + g + 8) * 2048 + h * 128 + tg * 2;
    #pragma unroll
    for (int n = 0; n < 16; n++) {
        *(uint32_t*)(g_ch + ro0 + n*8) = pack_f16(oc[n][0] * il0, oc[n][1] * il0);
        *(uint32_t*)(g_ch + ro1 + n*8) = pack_f16(oc[n][2] * il1, oc[n][3] * il1);
    }
}

// ---------------- launcher --------------------------------------------------
extern "C" void kernel_launch(void* const* d_in, const int* in_sizes, int n_in,
                              void* d_out, int out_size)
{
    (void)in_sizes; (void)n_in; (void)out_size;
    const float* x      = (const float*)d_in[0];
    const float* W_in   = (const float*)d_in[1];
    const float* b_in   = (const float*)d_in[2];
    const float* conv_w = (const float*)d_in[3];
    const float* conv_b = (const float*)d_in[4];
    const float* W_out  = (const float*)d_in[5];
    const float* b_out  = (const float*)d_in[6];
    float* out = (float*)d_out;

    __half *p_qkvh, *p_xh, *p_w1h, *p_w2h, *p_ch;
    cudaGetSymbolAddress((void**)&p_qkvh, g_qkvh);
    cudaGetSymbolAddress((void**)&p_xh,  g_xh);
    cudaGetSymbolAddress((void**)&p_w1h, g_w1h);
    cudaGetSymbolAddress((void**)&p_w2h, g_w2h);
    cudaGetSymbolAddress((void**)&p_ch,  g_ch);

    cudaFuncSetAttribute(gemm_fp16,
                         cudaFuncAttributeMaxDynamicSharedMemorySize, GEMMH_SMEM);
    cudaFuncSetAttribute(attn_mma,
                         cudaFuncAttributeMaxDynamicSharedMemorySize, ATTN_SMEM);

    // launch order keeps gemm_fp16 in ncu's capture slot
    rope_table_kernel<<<(S_*HROT + 255)/256, 256>>>();
    split_x_kernel<<<(T_*E_ + 255)/256, 256>>>(x);
    transpose_h_kernel<<<dim3(QKV_/32, E_/32), dim3(32,8)>>>(W_in, p_w1h, E_, QKV_);

    // GEMM1: qkv = x @ W_in + b_in  (fp16 output)
    gemm_fp16<<<dim3(QKV_/128, T_/128), 256, GEMMH_SMEM>>>(
        p_xh, p_w1h, b_in, nullptr, p_qkvh, QKV_);

    transpose_h_kernel<<<dim3(E_/32, E_/32), dim3(32,8)>>>(W_out, p_w2h, E_, E_);

    conv_rope_tiled<<<dim3(T_/32, 24), 256>>>(conv_w, conv_b);

    attn_mma<<<dim3(16, H_, B_), 256, ATTN_SMEM>>>();

    // GEMM2: out = ctx @ W_out + b_out  (fp32 output)
    gemm_fp16<<<dim3(E_/128, T_/128), 256, GEMMH_SMEM>>>(
        p_ch, p_w2h, b_out, out, nullptr, E_);
}

// round 17
// speedup vs baseline: 1.0091x; 1.0091x over previous
#include <cuda_runtime.h>
#include <cuda_bf16.h>
#include <cuda_fp16.h>
#include <math.h>
#include <stdint.h>

#define B_    2
#define S_    2048
#define E_    2048
#define H_    16
#define HKV_  4
#define D_    128
#define QKV_  3072
#define T_    (B_*S_)      // 4096
#define HROT  64           // ROT_DIM/2

// ---------------- scratch ----------------------------------------------------
__device__ __half g_qkvh[T_*QKV_];            // after GEMM1 (fp16)
__device__ __half g_xh[T_*E_];                // x as fp16
__device__ __half g_w1h[QKV_*E_];             // W_in^T fp16
__device__ __half g_w2h[E_*E_];               // W_out^T fp16
__device__ __half g_ch[T_*E_];                // ctx fp16
__device__ __half g_qh[T_*H_*D_];             // q fp16 (scaled, roped)
__device__ __half g_kh[T_*HKV_*D_];           // k fp16 (roped)
__device__ __half g_vh[T_*HKV_*D_];           // v fp16
__device__ float g_cos [S_*HROT];
__device__ float g_sin [S_*HROT];

// ---------------- helpers ---------------------------------------------------
__device__ __forceinline__ uint32_t su32(const void* p) {
    return (uint32_t)__cvta_generic_to_shared(p);
}
__device__ __forceinline__ void cp16(uint32_t dst, const void* src) {
    asm volatile("cp.async.cg.shared.global [%0], [%1], 16;\n"
                 :: "r"(dst), "l"(__cvta_generic_to_global(src)) : "memory");
}
__device__ __forceinline__ void mma16816h(float* c, const uint32_t* a, const uint32_t* b) {
    asm volatile(
        "mma.sync.aligned.m16n8k16.row.col.f32.f16.f16.f32 "
        "{%0,%1,%2,%3}, {%4,%5,%6,%7}, {%8,%9}, {%0,%1,%2,%3};"
        : "+f"(c[0]), "+f"(c[1]), "+f"(c[2]), "+f"(c[3])
        : "r"(a[0]), "r"(a[1]), "r"(a[2]), "r"(a[3]), "r"(b[0]), "r"(b[1]));
}
__device__ __forceinline__ void ldmx4(uint32_t* r, uint32_t addr) {
    asm volatile("ldmatrix.sync.aligned.m8n8.x4.shared.b16 {%0,%1,%2,%3}, [%4];"
                 : "=r"(r[0]), "=r"(r[1]), "=r"(r[2]), "=r"(r[3]) : "r"(addr));
}
__device__ __forceinline__ void ldmx4t(uint32_t* r, uint32_t addr) {
    asm volatile("ldmatrix.sync.aligned.m8n8.x4.trans.shared.b16 {%0,%1,%2,%3}, [%4];"
                 : "=r"(r[0]), "=r"(r[1]), "=r"(r[2]), "=r"(r[3]) : "r"(addr));
}
__device__ __forceinline__ uint32_t pack_f16(float a, float b) {
    __half2 v = __floats2half2_rn(a, b);
    return *(uint32_t*)&v;
}
__device__ __forceinline__ uint32_t ex2_f16x2(uint32_t in) {
    uint32_t r;
    asm("ex2.approx.f16x2 %0, %1;" : "=r"(r) : "r"(in));
    return r;
}

// ---------------- rotary tables (double exp for inv_freq, float trig) --------
__global__ void rope_table_kernel() {
    int idx = blockIdx.x * blockDim.x + threadIdx.x;
    if (idx >= S_*HROT) return;
    int i = idx % HROT;
    int s = idx / HROT;
    const double L = 9.210340371976184; // ln(10000)
    double inv_d = exp(-(double)i / 64.0 * L);
    float  inv_f = (float)inv_d;
    float  ang_f = __fmul_rn((float)s, inv_f); // float32 angle like numpy
    g_cos[idx] = cosf(ang_f);
    g_sin[idx] = sinf(ang_f);
}

// ---------------- x -> fp16 --------------------------------------------------
__global__ void split_x_kernel(const float* __restrict__ x) {
    int idx = blockIdx.x * blockDim.x + threadIdx.x;
    if (idx >= T_*E_) return;
    g_xh[idx] = __float2half(x[idx]);
}

// ---------------- transpose weights -> fp16: W[R][C] -> Wt[C][R] -------------
__global__ void transpose_h_kernel(const float* __restrict__ W,
                                   __half* __restrict__ Th, int R, int C) {
    __shared__ float tile[32][33];
    int c0 = blockIdx.x * 32, r0 = blockIdx.y * 32;
    for (int j = threadIdx.y; j < 32; j += 8)
        tile[j][threadIdx.x] = W[(size_t)(r0 + j) * C + c0 + threadIdx.x];
    __syncthreads();
    for (int j = threadIdx.y; j < 32; j += 8)
        Th[(size_t)(c0 + j) * R + r0 + threadIdx.x] = __float2half(tile[threadIdx.x][j]);
}

// ---------------- fp16 GEMM: 128x128 tile, 2 CTAs/SM, 3-stage ring ----------
// (at the legacy-HMMA instruction-rate ceiling — frozen)
// Ch != nullptr -> write fp16 to Ch; else write fp32 to C.
#define G3STR 144
#define G3A (128*G3STR)        // 18432
#define G3STAGE (2*G3A)        // 36864
#define GEMMH_SMEM (3*G3STAGE) // 110592

__global__ __launch_bounds__(256, 2) void gemm_fp16(
    const __half* __restrict__ A, const __half* __restrict__ Bm,
    const float* __restrict__ bias, float* __restrict__ C,
    __half* __restrict__ Ch, int N)
{
    extern __shared__ char sm8[];
    int tid = threadIdx.x, lane = tid & 31, wid = tid >> 5;
    int g = lane >> 2, tg = lane & 3;
    int wm = wid & 1, wn = wid >> 1;          // 2m x 4n
    int m0 = blockIdx.y * 128, n0 = blockIdx.x * 128;
    uint32_t smb = su32(sm8);

    float acc[4][4][4];
    #pragma unroll
    for (int mi = 0; mi < 4; mi++)
        #pragma unroll
        for (int nj = 0; nj < 4; nj++)
            #pragma unroll
            for (int q = 0; q < 4; q++) acc[mi][nj][q] = 0.f;

    auto issue = [&](int chunk, int s) {
        uint32_t bb = smb + s * G3STAGE;
        int k0 = chunk * 64;
        #pragma unroll
        for (int j = 0; j < 8; j++) {
            int idx = tid + j * 256;
            if (idx < 1024) {
                int r = idx >> 3, c = idx & 7;
                cp16(bb + r * G3STR + c * 16,
                     A + (size_t)(m0 + r) * 2048 + k0 + c * 8);
            } else {
                int o = idx - 1024;
                int r = o >> 3, c = o & 7;
                cp16(bb + G3A + r * G3STR + c * 16,
                     Bm + (size_t)(n0 + r) * 2048 + k0 + c * 8);
            }
        }
        asm volatile("cp.async.commit_group;\n" ::: "memory");
    };

    uint32_t a_base = (uint32_t)(wm * 64 + (lane & 15)) * G3STR + (lane >> 4) * 16;
    uint32_t b_base = (uint32_t)(wn * 32 + (lane & 7) + ((lane >> 4) * 8)) * G3STR
                    + ((lane >> 3) & 1) * 16;

    issue(0, 0);
    issue(1, 1);
    for (int i = 0; i < 32; i++) {
        if (i < 30) {
            asm volatile("cp.async.wait_group 1;\n" ::: "memory");
        } else {
            asm volatile("cp.async.wait_group 0;\n" ::: "memory");
        }
        __syncthreads();
        if (i < 30) issue(i + 2, (i + 2) % 3);

        uint32_t uA = smb + (i % 3) * G3STAGE;
        uint32_t uB = uA + G3A;

        #pragma unroll
        for (int ks = 0; ks < 4; ks++) {
            int kb = ks * 32;   // bytes
            uint32_t af[4][4], bf[4][2];
            #pragma unroll
            for (int mi = 0; mi < 4; mi++)
                ldmx4(af[mi], uA + a_base + mi * 16 * G3STR + kb);
            #pragma unroll
            for (int njp = 0; njp < 2; njp++)
                ldmx4(&bf[njp*2][0], uB + b_base + njp * 16 * G3STR + kb);
            #pragma unroll
            for (int mi = 0; mi < 4; mi++)
                #pragma unroll
                for (int nj = 0; nj < 4; nj++)
                    mma16816h(acc[mi][nj], af[mi], bf[nj]);
        }
    }

    #pragma unroll
    for (int mi = 0; mi < 4; mi++)
        #pragma unroll
        for (int nj = 0; nj < 4; nj++) {
            int row = m0 + wm * 64 + mi * 16 + g;
            int col = n0 + wn * 32 + nj * 8 + tg * 2;
            float b0v = bias[col], b1v = bias[col + 1];
            float o00 = acc[mi][nj][0] + b0v, o01 = acc[mi][nj][1] + b1v;
            float o10 = acc[mi][nj][2] + b0v, o11 = acc[mi][nj][3] + b1v;
            if (Ch) {
                *(uint32_t*)(Ch + (size_t)row * N + col)       = pack_f16(o00, o01);
                *(uint32_t*)(Ch + (size_t)(row + 8) * N + col) = pack_f16(o10, o11);
            } else {
                float2 v0 = { o00, o01 };
                float2 v1 = { o10, o11 };
                *(float2*)(C + (size_t)row * N + col) = v0;
                *(float2*)(C + (size_t)(row + 8) * N + col) = v1;
            }
        }
}

// ---------------- tiled conv + rope -> fp16 q/k/v (fp16 qkv input) ----------
__global__ __launch_bounds__(256) void conv_rope_tiled(
    const float* __restrict__ conv_w, const float* __restrict__ conv_b)
{
    __shared__ float tile[35*128];
    __shared__ float cw[128*4];
    __shared__ float cb[128];

    int tid = threadIdx.x;
    int t0  = blockIdx.x * 32;
    int hb  = blockIdx.y;            // 0..23
    int c0  = hb * 128;
    int b   = t0 / S_;
    int s0  = t0 % S_;
    const float scale = 0.08838834764831845f; // 1/sqrt(128)

    for (int i = tid; i < 512; i += 256) cw[i] = conv_w[c0*4 + i];
    if (tid < 128) cb[tid] = conv_b[c0 + tid];

    for (int i = tid; i < 35*128; i += 256) {
        int r = i >> 7, c = i & 127;
        int s = s0 + r - 3;
        tile[i] = (s >= 0)
            ? __half2float(g_qkvh[(size_t)(b*S_ + s)*QKV_ + c0 + c]) : 0.f;
    }
    __syncthreads();

    if (hb < 20) {
        #pragma unroll
        for (int p = tid; p < 32*64; p += 256) {
            int sl = p >> 6, i = p & 63;
            int s = s0 + sl;
            float a1 = cb[i], a2 = cb[i + 64];
            #pragma unroll
            for (int k = 0; k < 4; k++) {
                a1 = fmaf(tile[(sl + k)*128 + i],      cw[i*4 + k],        a1);
                a2 = fmaf(tile[(sl + k)*128 + i + 64], cw[(i + 64)*4 + k], a2);
            }
            float cs = g_cos[s*HROT + i], sn = g_sin[s*HROT + i];
            float r1 = a1*cs - a2*sn;
            float r2 = a2*cs + a1*sn;
            if (hb < 16) {
                r1 *= scale; r2 *= scale;
                size_t o = (size_t)(b*S_ + s)*2048 + hb*128 + i;
                g_qh[o]    = __float2half(r1);
                g_qh[o+64] = __float2half(r2);
            } else {
                size_t o = (size_t)(b*S_ + s)*512 + (hb - 16)*128 + i;
                g_kh[o]    = __float2half(r1);
                g_kh[o+64] = __float2half(r2);
            }
        }
    } else {
        #pragma unroll
        for (int p = tid; p < 32*128; p += 256) {
            int sl = p >> 7, c = p & 127;
            int s = s0 + sl;
            float a1 = cb[c];
            #pragma unroll
            for (int k = 0; k < 4; k++)
                a1 = fmaf(tile[(sl + k)*128 + c], cw[c*4 + k], a1);
            g_vh[(size_t)(b*S_ + s)*512 + (hb - 20)*128 + c] = __float2half(a1);
        }
    }
}

// ---------------- HMMA flash attention (causal, GQA), all fp16 --------------
// 2-stage KV ring, 1 sync/kb, 2 CTAs/SM.
// Softmax: ex2.approx.f16x2 (P fragments produced directly);
// row-sum l via MMA against an all-ones B fragment (fp32 acc, same rescale).
#define ASTR 136                       // halves per smem row
#define ASTRB 272                      // bytes per smem row
#define AQ_ELEMS (128*ASTR)            // 17408 halves
#define AKV_ELEMS (2*64*ASTR)          // 17408 halves (K + V)
#define ATTN_SMEM ((AQ_ELEMS + 2*AKV_ELEMS) * 2)   // 104448 bytes

__global__ __launch_bounds__(256, 2) void attn_mma() {
    extern __shared__ __half smH[];
    __half* sQ = smH;

    int tid = threadIdx.x, lane = tid & 31, w = tid >> 5;
    int g = lane >> 2, tg = lane & 3;
    int qblk = 15 - (int)blockIdx.x;
    int h = blockIdx.y, b = blockIdx.z;
    int hkv = h >> 2;
    int q0 = qblk * 128;
    size_t bS = (size_t)b * S_;

    // ---- issue Q ----
    {
        #pragma unroll
        for (int j = 0; j < 8; j++) {
            int i = tid + j * 256;
            int r = i >> 4, c = i & 15;
            cp16(su32(sQ + r * ASTR + c * 8),
                 g_qh + (bS + q0 + r) * 2048 + h * 128 + c * 8);
        }
        asm volatile("cp.async.commit_group;\n" ::: "memory");
    }

    auto issueKV = [&](int kb, int buf) {
        __half* kv = smH + AQ_ELEMS + buf * AKV_ELEMS;
        int k0 = kb * 64;
        #pragma unroll
        for (int j = 0; j < 8; j++) {
            int i = tid + j * 256;
            int arr = i >> 10, o = i & 1023;
            int r = o >> 4, c = o & 15;
            size_t off = (bS + k0 + r) * 512 + hkv * 128 + c * 8;
            const __half* src = (arr == 0) ? (g_kh + off) : (g_vh + off);
            cp16(su32(kv + arr * (64*ASTR) + r * ASTR + c * 8), src);
        }
        asm volatile("cp.async.commit_group;\n" ::: "memory");
    };

    float oc[16][4];
    #pragma unroll
    for (int n = 0; n < 16; n++)
        #pragma unroll
        for (int q = 0; q < 4; q++) oc[n][q] = 0.f;
    float lc[4] = {0.f, 0.f, 0.f, 0.f};     // l via ones-MMA (use [0], [2])
    float m0 = -1e30f, m1 = -1e30f;

    const uint32_t ONES2 = 0x3C003C00u;     // fp16 {1.0, 1.0}
    uint32_t onesb[2] = { ONES2, ONES2 };
    const float L2E = 1.4426950408889634f;

    int nkb = 2 * qblk + 2;
    issueKV(0, 0);

    int row0 = q0 + w * 16;

    // ldmatrix lane addressing (bytes)
    uint32_t q_lm = (uint32_t)(w * 16 + (lane & 15)) * ASTRB + (lane >> 4) * 16;
    uint32_t k_lm = (uint32_t)((lane & 7) + ((lane >> 4) * 8)) * ASTRB
                  + ((lane >> 3) & 1) * 16;

    // V ldmatrix.trans lane components (half units)
    int v_t  = lane >> 3;
    int v_kr = ((v_t & 1) << 3) + (lane & 7);
    int v_dc = (v_t >> 1) << 3;

    uint32_t uQ = su32(smH);

    for (int kb = 0; kb < nkb; kb++) {
        asm volatile("cp.async.wait_group 0;\n" ::: "memory");
        __syncthreads();
        if (kb + 1 < nkb) issueKV(kb + 1, (kb + 1) & 1);

        int k0 = kb * 64;
        bool active = (k0 <= row0 + 15);
        if (active) {
            __half* sV = smH + AQ_ELEMS + (kb & 1) * AKV_ELEMS + 64*ASTR;
            uint32_t uK = uQ + (AQ_ELEMS + (kb & 1) * AKV_ELEMS) * 2;

            float sc[8][4];
            #pragma unroll
            for (int j = 0; j < 8; j++)
                #pragma unroll
                for (int q = 0; q < 4; q++) sc[j][q] = 0.f;

            // ---- S = Q K^T (fp16, ldmatrix frags) ----
            #pragma unroll
            for (int ks = 0; ks < 8; ks++) {
                int kbyte = ks * 32;
                uint32_t qf[4], kf[8][2];
                ldmx4(qf, uQ + q_lm + kbyte);
                #pragma unroll
                for (int npk = 0; npk < 4; npk++)
                    ldmx4(&kf[npk*2][0], uK + k_lm + npk * 16 * ASTRB + kbyte);
                #pragma unroll
                for (int j = 0; j < 8; j++)
                    mma16816h(sc[j], qf, kf[j]);
            }

            // ---- causal mask (boundary tiles only) ----
            if (k0 + 63 > row0) {
                #pragma unroll
                for (int j = 0; j < 8; j++) {
                    int col = k0 + j*8 + tg*2;
                    int r0r = row0 + g, r1r = row0 + g + 8;
                    if (col     > r0r) sc[j][0] = -1e30f;
                    if (col + 1 > r0r) sc[j][1] = -1e30f;
                    if (col     > r1r) sc[j][2] = -1e30f;
                    if (col + 1 > r1r) sc[j][3] = -1e30f;
                }
            }

            // ---- online softmax: max via shfl; P = ex2.f16x2 directly ----
            float nm0 = -1e30f, nm1 = -1e30f;
            #pragma unroll
            for (int j = 0; j < 8; j++) {
                nm0 = fmaxf(nm0, fmaxf(sc[j][0], sc[j][1]));
                nm1 = fmaxf(nm1, fmaxf(sc[j][2], sc[j][3]));
            }
            nm0 = fmaxf(nm0, __shfl_xor_sync(0xffffffff, nm0, 1));
            nm0 = fmaxf(nm0, __shfl_xor_sync(0xffffffff, nm0, 2));
            nm1 = fmaxf(nm1, __shfl_xor_sync(0xffffffff, nm1, 1));
            nm1 = fmaxf(nm1, __shfl_xor_sync(0xffffffff, nm1, 2));
            float mn0 = fmaxf(m0, nm0), mn1 = fmaxf(m1, nm1);
            float fac0 = __expf(m0 - mn0), fac1 = __expf(m1 - mn1);
            m0 = mn0; m1 = mn1;
            float nms0 = -mn0 * L2E, nms1 = -mn1 * L2E;

            uint32_t ph[8][2];
            #pragma unroll
            for (int j = 0; j < 8; j++) {
                float t0 = fmaf(sc[j][0], L2E, nms0);
                float t1 = fmaf(sc[j][1], L2E, nms0);
                float t2 = fmaf(sc[j][2], L2E, nms1);
                float t3 = fmaf(sc[j][3], L2E, nms1);
                ph[j][0] = ex2_f16x2(pack_f16(t0, t1));
                ph[j][1] = ex2_f16x2(pack_f16(t2, t3));
            }

            // ---- rescale O and l ----
            lc[0] *= fac0; lc[1] *= fac0; lc[2] *= fac1; lc[3] *= fac1;
            #pragma unroll
            for (int n = 0; n < 16; n++) {
                oc[n][0] *= fac0; oc[n][1] *= fac0;
                oc[n][2] *= fac1; oc[n][3] *= fac1;
            }

            // ---- O += P V ; l += P @ ones ----
            #pragma unroll
            for (int kc = 0; kc < 4; kc++) {
                uint32_t ah[4] = { ph[2*kc][0], ph[2*kc][1], ph[2*kc+1][0], ph[2*kc+1][1] };
                mma16816h(lc, ah, onesb);       // row sums
                #pragma unroll
                for (int np = 0; np < 8; np++) {
                    int vo = (kc*16 + v_kr) * ASTR + np*16 + v_dc;
                    uint32_t vh[4];
                    ldmx4t(vh, su32(sV + vo));
                    mma16816h(oc[2*np],     ah, vh);
                    mma16816h(oc[2*np + 1], ah, vh + 2);
                }
            }
        }
    }

    // ---- epilogue: normalize + fp16 ctx write ----
    float il0 = 1.0f / lc[0], il1 = 1.0f / lc[2];
    size_t ro0 = (bS + row0 + g) * 2048 + h * 128 + tg * 2;
    size_t ro1 = (bS + row0 + g + 8) * 2048 + h * 128 + tg * 2;
    #pragma unroll
    for (int n = 0; n < 16; n++) {
        *(uint32_t*)(g_ch + ro0 + n*8) = pack_f16(oc[n][0] * il0, oc[n][1] * il0);
        *(uint32_t*)(g_ch + ro1 + n*8) = pack_f16(oc[n][2] * il1, oc[n][3] * il1);
    }
}

// ---------------- launcher --------------------------------------------------
extern "C" void kernel_launch(void* const* d_in, const int* in_sizes, int n_in,
                              void* d_out, int out_size)
{
    (void)in_sizes; (void)n_in; (void)out_size;
    const float* x      = (const float*)d_in[0];
    const float* W_in   = (const float*)d_in[1];
    const float* b_in   = (const float*)d_in[2];
    const float* conv_w = (const float*)d_in[3];
    const float* conv_b = (const float*)d_in[4];
    const float* W_out  = (const float*)d_in[5];
    const float* b_out  = (const float*)d_in[6];
    float* out = (float*)d_out;

    __half *p_qkvh, *p_xh, *p_w1h, *p_w2h, *p_ch;
    cudaGetSymbolAddress((void**)&p_qkvh, g_qkvh);
    cudaGetSymbolAddress((void**)&p_xh,  g_xh);
    cudaGetSymbolAddress((void**)&p_w1h, g_w1h);
    cudaGetSymbolAddress((void**)&p_w2h, g_w2h);
    cudaGetSymbolAddress((void**)&p_ch,  g_ch);

    cudaFuncSetAttribute(gemm_fp16,
                         cudaFuncAttributeMaxDynamicSharedMemorySize, GEMMH_SMEM);
    cudaFuncSetAttribute(attn_mma,
                         cudaFuncAttributeMaxDynamicSharedMemorySize, ATTN_SMEM);

    // launch order keeps gemm_fp16 in ncu's capture slot
    rope_table_kernel<<<(S_*HROT + 255)/256, 256>>>();
    split_x_kernel<<<(T_*E_ + 255)/256, 256>>>(x);
    transpose_h_kernel<<<dim3(QKV_/32, E_/32), dim3(32,8)>>>(W_in, p_w1h, E_, QKV_);

    // GEMM1: qkv = x @ W_in + b_in  (fp16 output)
    gemm_fp16<<<dim3(QKV_/128, T_/128), 256, GEMMH_SMEM>>>(
        p_xh, p_w1h, b_in, nullptr, p_qkvh, QKV_);

    transpose_h_kernel<<<dim3(E_/32, E_/32), dim3(32,8)>>>(W_out, p_w2h, E_, E_);

    conv_rope_tiled<<<dim3(T_/32, 24), 256>>>(conv_w, conv_b);

    attn_mma<<<dim3(16, H_, B_), 256, ATTN_SMEM>>>();

    // GEMM2: out = ctx @ W_out + b_out  (fp32 output)
    gemm_fp16<<<dim3(E_/128, T_/128), 256, GEMMH_SMEM>>>(
        p_ch, p_w2h, b_out, out, nullptr, E_);
}